// round 12
// baseline (speedup 1.0000x reference)
#include <cuda_runtime.h>

// CostVolume: out[b,c,h,w,d] = (w>=d) ? L[b,c,h,w] - R[b,c,h,w-d] : 0
// Shapes: B=4, C=32, H=128, W=240, D=24.  Rows = B*C*H = 16384.
// Pure HBM-store-bound: 377.5 MB out + 31.5 MB in.

#define W_DIM 240
#define D_DIM 24
#define NTHREADS 288                      // 1440 float4 per row / 5 iters
#define F4_PER_ROW ((W_DIM * D_DIM) / 4)  // 1440

__global__ __launch_bounds__(NTHREADS)
void cost_volume_kernel(const float* __restrict__ left,
                        const float* __restrict__ right,
                        float* __restrict__ out)
{
    __shared__ float Ls[W_DIM];
    __shared__ float Rs[W_DIM];

    const int row = blockIdx.x;
    const int t   = threadIdx.x;

    const float* lrow = left  + (size_t)row * W_DIM;
    const float* rrow = right + (size_t)row * W_DIM;

    if (t < W_DIM) {
        Ls[t] = lrow[t];
        Rs[t] = rrow[t];
    }
    __syncthreads();

    float4* orow = reinterpret_cast<float4*>(out + (size_t)row * (W_DIM * D_DIM));

    #pragma unroll
    for (int it = 0; it < F4_PER_ROW / NTHREADS; ++it) {
        const int idx = t + it * NTHREADS;     // 0..1439, consecutive across warp
        const int w   = idx / 6;               // output column
        const int q   = idx - w * 6;           // which float4 within the D=24 run
        const int d0  = q * 4;

        const float lv = Ls[w];

        // clamp smem index so the (predicated-off) load is always in-bounds
        int s0 = w - d0;
        int s1 = s0 - 1;
        int s2 = s0 - 2;
        int s3 = s0 - 3;

        float4 v;
        v.x = (s0 >= 0) ? (lv - Rs[s0 < 0 ? 0 : s0]) : 0.0f;
        v.y = (s1 >= 0) ? (lv - Rs[s1 < 0 ? 0 : s1]) : 0.0f;
        v.z = (s2 >= 0) ? (lv - Rs[s2 < 0 ? 0 : s2]) : 0.0f;
        v.w = (s3 >= 0) ? (lv - Rs[s3 < 0 ? 0 : s3]) : 0.0f;

        __stcs(&orow[idx], v);   // streaming store: don't pollute L2 with 377 MB
    }
}

extern "C" void kernel_launch(void* const* d_in, const int* in_sizes, int n_in,
                              void* d_out, int out_size)
{
    const float* left  = (const float*)d_in[0];
    const float* right = (const float*)d_in[1];
    float* out = (float*)d_out;

    const int rows = in_sizes[0] / W_DIM;   // B*C*H = 16384
    cost_volume_kernel<<<rows, NTHREADS>>>(left, right, out);
}

// round 13
// speedup vs baseline: 1.0116x; 1.0116x over previous
#include <cuda_runtime.h>

// CostVolume: out[b,c,h,w,d] = (w>=d) ? L[b,c,h,w] - R[b,c,h,w-d] : 0
// Shapes: B=4, C=32, H=128, W=240, D=24.  Rows = B*C*H = 16384.
// Pure HBM-store-bound: 377.5 MB out + 31.5 MB in.

#define W_DIM 240
#define D_DIM 24
#define NTHREADS 288                      // 1440 float4 per row / 5 iters
#define F4_PER_ROW ((W_DIM * D_DIM) / 4)  // 1440

__global__ __launch_bounds__(NTHREADS)
void cost_volume_kernel(const float* __restrict__ left,
                        const float* __restrict__ right,
                        float* __restrict__ out)
{
    __shared__ float Ls[W_DIM];
    __shared__ float Rs[W_DIM];

    const int row = blockIdx.x;
    const int t   = threadIdx.x;

    const float* lrow = left  + (size_t)row * W_DIM;
    const float* rrow = right + (size_t)row * W_DIM;

    if (t < W_DIM) {
        Ls[t] = lrow[t];
        Rs[t] = rrow[t];
    }
    __syncthreads();

    float4* orow = reinterpret_cast<float4*>(out + (size_t)row * (W_DIM * D_DIM));

    #pragma unroll
    for (int it = 0; it < F4_PER_ROW / NTHREADS; ++it) {
        const int idx = t + it * NTHREADS;     // 0..1439, consecutive across warp
        const int w   = idx / 6;               // output column
        const int q   = idx - w * 6;           // which float4 within the D=24 run
        const int d0  = q * 4;

        const float lv = Ls[w];

        // clamp smem index so the (predicated-off) load is always in-bounds
        int s0 = w - d0;
        int s1 = s0 - 1;
        int s2 = s0 - 2;
        int s3 = s0 - 3;

        float4 v;
        v.x = (s0 >= 0) ? (lv - Rs[s0 < 0 ? 0 : s0]) : 0.0f;
        v.y = (s1 >= 0) ? (lv - Rs[s1 < 0 ? 0 : s1]) : 0.0f;
        v.z = (s2 >= 0) ? (lv - Rs[s2 < 0 ? 0 : s2]) : 0.0f;
        v.w = (s3 >= 0) ? (lv - Rs[s3 < 0 ? 0 : s3]) : 0.0f;

        __stcs(&orow[idx], v);   // streaming store: don't pollute L2 with 377 MB
    }
}

extern "C" void kernel_launch(void* const* d_in, const int* in_sizes, int n_in,
                              void* d_out, int out_size)
{
    const float* left  = (const float*)d_in[0];
    const float* right = (const float*)d_in[1];
    float* out = (float*)d_out;

    const int rows = in_sizes[0] / W_DIM;   // B*C*H = 16384
    cost_volume_kernel<<<rows, NTHREADS>>>(left, right, out);
}